// round 16
// baseline (speedup 1.0000x reference)
#include <cuda_runtime.h>
#include <cstdint>

#define PB 32
#define PS 1024
#define PNODE 256
#define PDEP 64
#define PR 50
#define PL 16
#define PE 128
#define PF 320
#define NEDGE (PB * PE)     // 4096
#define NTOT (PL * NEDGE)   // 65536
#define MAXCHUNK 1200
#define PREPB 64
#define MAXSLOT 288

// ---------------- scratch --------------------------------------------------
__device__ float g_child[PB * PS * PDEP];
__device__ float g_pmsg[PL * NEDGE * PDEP];
__device__ float g_W2T[PR * 32 * 32 * 4];        // [r][d2][k2][4] quad layout
__device__ int   g_gsort[NTOT];
__device__ int   g_gcnt[PR];
__device__ int   g_gbase[PR + 1];
__device__ int   g_gcur[PR];
__device__ int   g_chunk_rel[MAXCHUNK];
__device__ int   g_chunk_start[MAXCHUNK];
__device__ int   g_chunk_ne[MAXCHUNK];
__device__ int   g_nchunks;
__device__ unsigned int g_ticket;
__device__ int   g_slots[PB * PL * MAXSLOT];     // (r<<7)|e, bit15 = pad
__device__ int   g_nslot[PB * PL];
__device__ int   g_hkey[NTOT];
__device__ int   g_hidx[NTOT];
__device__ unsigned int g_pbar;

// ---------------- helpers --------------------------------------------------
__device__ __forceinline__ void fma2(unsigned long long& acc,
                                     unsigned long long a, unsigned long long b) {
    asm("fma.rn.f32x2 %0, %1, %2, %0;" : "+l"(acc) : "l"(a), "l"(b));
}
__device__ __forceinline__ unsigned long long pack2(float x, float y) {
    unsigned long long v;
    asm("mov.b64 %0, {%1,%2};" : "=l"(v) : "r"(__float_as_uint(x)), "r"(__float_as_uint(y)));
    return v;
}
__device__ __forceinline__ void unpack2(unsigned long long v, float& x, float& y) {
    unsigned int lo, hi;
    asm("mov.b64 {%0,%1}, %2;" : "=r"(lo), "=r"(hi) : "l"(v));
    x = __uint_as_float(lo); y = __uint_as_float(hi);
}
__device__ __forceinline__ float hsum2(unsigned long long v) {
    float x, y; unpack2(v, x, y); return x + y;
}
__device__ __forceinline__ unsigned int smem_u32(const void* p) {
    return (unsigned int)__cvta_generic_to_shared(p);
}
__device__ __forceinline__ unsigned int mapa_sh(unsigned int addr, unsigned int rank) {
    unsigned int r;
    asm("mapa.shared::cluster.u32 %0, %1, %2;" : "=r"(r) : "r"(addr), "r"(rank));
    return r;
}
__device__ __forceinline__ void st_dsmem64(unsigned int addr, unsigned long long v) {
    asm volatile("st.shared::cluster.b64 [%0], %1;" :: "r"(addr), "l"(v) : "memory");
}
#define MBAR_INIT(addr, cnt) \
    asm volatile("mbarrier.init.shared.b64 [%0], %1;" :: "r"(addr), "r"(cnt) : "memory")
__device__ __forceinline__ void mbar_arrive_rel_cluster(unsigned int addr) {
    asm volatile("mbarrier.arrive.release.cluster.shared::cluster.b64 _, [%0];"
                 :: "r"(addr) : "memory");
}
__device__ __forceinline__ void mbar_wait_acq_cluster(unsigned int addr, unsigned int parity) {
    unsigned int done;
    do {
        asm volatile("{\n\t.reg .pred p;\n\t"
            "mbarrier.try_wait.parity.acquire.cluster.shared::cta.b64 p, [%1], %2, 0x989680;\n\t"
            "selp.b32 %0, 1, 0, p;\n\t}"
            : "=r"(done) : "r"(addr), "r"(parity) : "memory");
    } while (!done);
}
#define CLUSTER_ARRIVE() asm volatile("barrier.cluster.arrive.aligned;" ::: "memory")
#define CLUSTER_WAIT()   asm volatile("barrier.cluster.wait.aligned;" ::: "memory")

// ---------------- launch 0: flag resets (tiny) ------------------------------
__global__ void k_flags() {
    if (threadIdx.x == 0) { g_ticket = 0; g_pbar = 0; }
    if (threadIdx.x < PR) g_gcnt[threadIdx.x] = 0;
}

// ---------------- prep barrier ---------------------------------------------
__device__ __forceinline__ void psync(int* pc) {
    __syncthreads();
    (*pc)++;
    if (threadIdx.x == 0) {
        __threadfence();
        atomicAdd(&g_pbar, 1);
        unsigned int target = (unsigned int)(PREPB * (*pc));
        while (*(volatile unsigned int*)&g_pbar < target) { }
        __threadfence();
    }
    __syncthreads();
}

// ---------------- launch 1: preprocessing + init (merged) -------------------
__global__ void __launch_bounds__(256, 2)
k_prep(const int* __restrict__ rels, const int* __restrict__ heads,
       const float* __restrict__ W, const float* __restrict__ ctx,
       float* __restrict__ out) {
    int bid = blockIdx.x;
    int tid = threadIdx.x;
    int w = tid >> 5, lane = tid & 31;
    __shared__ int cnt[PR];
    __shared__ int hs2[2][128];
    __shared__ int srel[8][128];
    __shared__ int sb[PR], sch[PR];
    int pc = 0;

    // --- A-1: init work: out ctx-copy + child zero ---
    {
        const int64_t n_ctx = (int64_t)PB * PS * (PNODE / 4);
        const int64_t n_chd = (int64_t)PB * PS * (PDEP / 4);
        const int64_t total = n_ctx + n_chd;
        int64_t stride = (int64_t)PREPB * 256;
        for (int64_t i = (int64_t)bid * 256 + tid; i < total; i += stride) {
            if (i < n_ctx) {
                int64_t row = i >> 6, d4 = i & 63;
                float4 v = ((const float4*)ctx)[i];
                *(float4*)&out[row * PF + d4 * 4] = v;
            } else {
                ((float4*)g_child)[i - n_ctx] = make_float4(0.f, 0.f, 0.f, 0.f);
            }
        }
    }

    // --- A0: build W2T k-pair-quad layout: [r][d2][k2][4] ---
    for (int qi = bid * 256 + tid; qi < PR * 32 * 32; qi += PREPB * 256) {
        int r = qi >> 10, rem = qi & 1023;
        int d2 = rem >> 5, k2 = rem & 31;
        const float* Wb = W + ((int64_t)r * PDEP + 2 * k2) * PF + PNODE + 2 * d2;
        float4 v;
        v.x = __ldg(&Wb[0]);
        v.y = __ldg(&Wb[PF]);
        v.z = __ldg(&Wb[1]);
        v.w = __ldg(&Wb[PF + 1]);
        *(float4*)&g_W2T[qi * 4] = v;
    }

    // --- A1: global rel histogram ---
    if (tid < PR) cnt[tid] = 0;
    __syncthreads();
    int ebase = bid * 1024;
    #pragma unroll
    for (int t = 0; t < 4; t++)
        atomicAdd(&cnt[rels[ebase + tid + t * 256]], 1);
    __syncthreads();
    if (tid < PR && cnt[tid] > 0) atomicAdd(&g_gcnt[tid], cnt[tid]);

    // --- A2: per (b,l) padded rel-quad slot lists ---
    {
        int task = bid * 8 + w;           // 0..511 = b*PL + l
        int b = task >> 4, l = task & 15;
        #pragma unroll
        for (int t = 0; t < 4; t++)
            srel[w][lane + 32 * t] = rels[b * (PL * PE) + l * PE + lane + 32 * t];
        __syncwarp();
        int c0 = 0, c1 = 0;
        int r1 = lane + 32;
        for (int j = 0; j < PE; j++) {
            int rv = srel[w][j];
            c0 += (rv == lane);
            c1 += (rv == r1);
        }
        int p0 = (c0 + 3) & ~3;
        int p1 = (r1 < PR) ? ((c1 + 3) & ~3) : 0;
        int s0 = p0, s1 = p1;
        #pragma unroll
        for (int o = 1; o < 32; o <<= 1) {
            int x0 = __shfl_up_sync(0xffffffffu, s0, o);
            int x1 = __shfl_up_sync(0xffffffffu, s1, o);
            if (lane >= o) { s0 += x0; s1 += x1; }
        }
        int tot0 = __shfl_sync(0xffffffffu, s0, 31);
        int tot1 = __shfl_sync(0xffffffffu, s1, 31);
        int off0 = s0 - p0;
        int off1 = tot0 + s1 - p1;
        int* dst = &g_slots[task * MAXSLOT];
        int o0 = off0;
        for (int j = 0; j < PE; j++)
            if (srel[w][j] == lane) dst[o0++] = (lane << 7) | j;
        while (o0 < off0 + p0) dst[o0++] = (lane << 7) | 0x8000;
        if (p1 > 0) {
            int o1 = off1;
            for (int j = 0; j < PE; j++)
                if (srel[w][j] == r1) dst[o1++] = (r1 << 7) | j;
            while (o1 < off1 + p1) dst[o1++] = (r1 << 7) | 0x8000;
        }
        if (lane == 31) g_nslot[task] = tot0 + tot1;
    }

    // --- A3: head rank-sort ---
    #pragma unroll
    for (int t = 0; t < 4; t++) {
        int task = bid * 8 + t * 2 + (tid >> 7);
        int l = task >> 5, b = task & 31;
        int e = tid & 127;
        int h = heads[b * (PL * PE) + l * PE + e];
        hs2[tid >> 7][e] = h;
        __syncthreads();
        int rank = 0;
        #pragma unroll 8
        for (int o = 0; o < PE; o++) {
            int ho = hs2[tid >> 7][o];
            rank += (ho < h) || (ho == h && o < e);
        }
        int base = l * NEDGE + b * PE;
        g_hkey[base + rank] = h;
        g_hidx[base + rank] = e;
        __syncthreads();
    }

    psync(&pc);

    // --- B: prefix + chunk worklist (block 0), 64-edge chunks ---
    if (bid == 0) {
        if (tid == 0) {
            int s = 0, nc = 0;
            for (int r = 0; r < PR; r++) {
                sb[r] = s;
                sch[r] = nc;
                int c = g_gcnt[r];
                s += c;
                nc += (c + 63) >> 6;
            }
            g_gbase[PR] = s;
            g_nchunks = nc;
        }
        __syncthreads();
        if (tid < PR) {
            int b0 = sb[tid];
            g_gbase[tid] = b0;
            g_gcur[tid] = b0;
            int c = g_gcnt[tid];
            int nc0 = sch[tid];
            for (int o = 0, k = 0; o < c; o += 64, k++) {
                g_chunk_rel[nc0 + k] = tid;
                g_chunk_start[nc0 + k] = b0 + o;
                g_chunk_ne[nc0 + k] = min(64, c - o);
            }
        }
    }

    psync(&pc);

    // --- C: global scatter with range reservation ---
    __shared__ int rbase[PR], rcur[PR];
    if (tid < PR) rcur[tid] = 0;
    __syncthreads();
    if (tid < PR) rbase[tid] = (cnt[tid] > 0) ? atomicAdd(&g_gcur[tid], cnt[tid]) : 0;
    __syncthreads();
    #pragma unroll
    for (int t = 0; t < 4; t++) {
        int idx = ebase + tid + t * 256;
        int r = rels[idx];
        int pos = rbase[r] + atomicAdd(&rcur[r], 1);
        int b = idx >> 11, l = (idx >> 7) & 15, e = idx & 127;
        g_gsort[pos] = (l << 12) | (b << 7) | e;
    }
}

// ---------------- launch 2: pmsg v3 (64-edge chunks, direct-W, occ 2) ------
#define PM_STRIDE 260
#define PM_SMEM (64 * PM_STRIDE * (int)sizeof(float))   // 66560

__global__ void __launch_bounds__(512, 2)
k_pmsg(const float* __restrict__ ctx, const float* __restrict__ W,
       const int* __restrict__ tails) {
    extern __shared__ float sm[];
    float* Fs = sm;                         // [64][260]
    __shared__ int seid[64];
    __shared__ int stail[64];
    __shared__ int s_chunk;
    int tid = threadIdx.x;

    while (true) {
        __syncthreads();                    // protect seid/Fs reuse
        if (tid == 0) s_chunk = (int)atomicAdd(&g_ticket, 1u);
        __syncthreads();
        int c = s_chunk;
        if (c >= g_nchunks) break;
        int r = g_chunk_rel[c];
        int start = g_chunk_start[c];
        int ne = g_chunk_ne[c];

        if (tid < 64) {
            int v = (tid < ne) ? __ldg(&g_gsort[start + tid]) : -1;
            seid[tid] = v;
            int tnode = 0;
            if (v >= 0) {
                int b = (v >> 7) & 31, l = v >> 12, e = v & 127;
                tnode = b * PS + __ldg(&tails[b * (PL * PE) + l * PE + e]);
            }
            stail[tid] = tnode;
        }
        __syncthreads();

        // gather ctx rows: 4096 float4 over 512 threads
        #pragma unroll
        for (int t = 0; t < 8; t++) {
            int idx = tid + t * 512;
            int row = idx >> 6, cc = idx & 63;
            float4 v = make_float4(0.f, 0.f, 0.f, 0.f);
            if (seid[row] >= 0)
                v = *(const float4*)&ctx[(int64_t)stail[row] * PNODE + cc * 4];
            *(float4*)&Fs[row * PM_STRIDE + cc * 4] = v;
        }
        __syncthreads();

        // compute: lane = e-group (e, e+32); warp kg -> k rows 4kg..4kg+3
        int eg = tid & 31;
        int kg = tid >> 5;
        const float* Wr = W + ((int64_t)r * PDEP + 4 * kg) * PF;  // warp-uniform
        unsigned long long acc[2][4];
        #pragma unroll
        for (int i = 0; i < 2; i++)
            #pragma unroll
            for (int j = 0; j < 4; j++) acc[i][j] = 0ull;

        #pragma unroll 4
        for (int d = 0; d < PNODE; d += 4) {
            ulonglong2 w0 = *(const ulonglong2*)&Wr[d];            // LDG broadcast
            ulonglong2 w1 = *(const ulonglong2*)&Wr[PF + d];
            ulonglong2 w2 = *(const ulonglong2*)&Wr[2 * PF + d];
            ulonglong2 w3 = *(const ulonglong2*)&Wr[3 * PF + d];
            ulonglong2 f0 = *(const ulonglong2*)&Fs[eg * PM_STRIDE + d];
            ulonglong2 f1 = *(const ulonglong2*)&Fs[(eg + 32) * PM_STRIDE + d];
            fma2(acc[0][0], f0.x, w0.x); fma2(acc[0][0], f0.y, w0.y);
            fma2(acc[0][1], f0.x, w1.x); fma2(acc[0][1], f0.y, w1.y);
            fma2(acc[0][2], f0.x, w2.x); fma2(acc[0][2], f0.y, w2.y);
            fma2(acc[0][3], f0.x, w3.x); fma2(acc[0][3], f0.y, w3.y);
            fma2(acc[1][0], f1.x, w0.x); fma2(acc[1][0], f1.y, w0.y);
            fma2(acc[1][1], f1.x, w1.x); fma2(acc[1][1], f1.y, w1.y);
            fma2(acc[1][2], f1.x, w2.x); fma2(acc[1][2], f1.y, w2.y);
            fma2(acc[1][3], f1.x, w3.x); fma2(acc[1][3], f1.y, w3.y);
        }

        #pragma unroll
        for (int i = 0; i < 2; i++) {
            int v = seid[eg + 32 * i];
            if (v >= 0) {
                int l = v >> 12, edge = v & 4095;
                float4 o = make_float4(hsum2(acc[i][0]), hsum2(acc[i][1]),
                                       hsum2(acc[i][2]), hsum2(acc[i][3]));
                *(float4*)&g_pmsg[((int64_t)l * NEDGE + edge) * PDEP + 4 * kg] = o;
            }
        }
    }
}

// ---------------- launch 3: chain (round-12/15 exact) -----------------------
#define CB_OFF 0
#define MS_OFF (128 * 68)
#define SLOT_OFF (MS_OFF + 128 * 32)
#define TL_OFF (SLOT_OFF + 16 * MAXSLOT)
#define HK_OFF (TL_OFF + 16 * 128)
#define HX_OFF (HK_OFF + 16 * 128)
#define NS_OFF (HX_OFF + 16 * 128)
#define CH_SMEM ((NS_OFF + 16) * (int)sizeof(float))

__global__ void __launch_bounds__(512, 1) __cluster_dims__(2, 1, 1)
k_chain(const int* __restrict__ tails, float* __restrict__ out) {
    extern __shared__ float sm[];
    float* Cb = sm + CB_OFF;                 // [128][68] gather tile
    float* Ms = sm + MS_OFF;                 // [128][32] own k-half msgs
    int* s_slot = (int*)(sm + SLOT_OFF);
    int* s_tl   = (int*)(sm + TL_OFF);
    int* s_hk   = (int*)(sm + HK_OFF);
    int* s_hx   = (int*)(sm + HX_OFF);
    int* s_ns   = (int*)(sm + NS_OFF);
    __shared__ unsigned long long s_mbar[2]; // [0]=A (msg), [1]=B (child)

    int b = blockIdx.x >> 1;
    unsigned int q = blockIdx.x & 1;
    int tid = threadIdx.x;

    unsigned int barA = smem_u32(&s_mbar[0]);
    unsigned int barB = smem_u32(&s_mbar[1]);
    if (tid == 0) { MBAR_INIT(barA, 1); MBAR_INIT(barB, 1); }

    // ---- prologue: stage all static per-layer data ----
    #pragma unroll
    for (int l2 = 0; l2 < PL; l2++)
        if (tid < MAXSLOT)
            s_slot[l2 * MAXSLOT + tid] = __ldg(&g_slots[(b * PL + l2) * MAXSLOT + tid]);
    #pragma unroll
    for (int t = 0; t < 4; t++) {
        int i = tid + t * 512;
        s_tl[i] = __ldg(&tails[b * (PL * PE) + i]);
    }
    #pragma unroll
    for (int l2 = 0; l2 < PL; l2++) {
        if (tid < 128) {
            s_hk[l2 * 128 + tid] = __ldg(&g_hkey[l2 * NEDGE + b * PE + tid]);
            s_hx[l2 * 128 + tid] = __ldg(&g_hidx[l2 * NEDGE + b * PE + tid]);
        }
    }
    if (tid < PL) s_ns[tid] = __ldg(&g_nslot[b * PL + tid]);
    __syncthreads();
    CLUSTER_ARRIVE(); CLUSTER_WAIT();       // peer mbarrier init visible

    unsigned int peerBarA = mapa_sh(barA, q ^ 1);
    unsigned int peerBarB = mapa_sh(barB, q ^ 1);
    unsigned int peerMs = mapa_sh(smem_u32(Ms), q ^ 1);

    float* childb = &g_child[b * PS * PDEP];

    for (int l = 0; l < PL; l++) {
        if (l == 0) {
            // Ms <- pmsg own k-half of all edges
            #pragma unroll
            for (int t = 0; t < 2; t++) {
                int idx = tid + t * 512;            // 1024 float4
                int e = idx >> 3, c4 = idx & 7;
                float4 v = __ldg((const float4*)&g_pmsg[
                    ((int64_t)(b * PE + e)) * PDEP + q * 32 + c4 * 4]);
                *(float4*)&Ms[e * 32 + c4 * 4] = v;
            }
            __syncthreads();
        } else {
            int nslot = s_ns[l];
            int nq = nslot >> 2;
            const int* slt = &s_slot[l * MAXSLOT];
            for (int i0 = 0; 2 * i0 + (int)q < nq; i0 += 32) {
                __syncthreads();
                // gather child rows for up to 32 own quads (128 rows)
                #pragma unroll
                for (int t = 0; t < 4; t++) {
                    int idx = tid + t * 512;
                    int row = idx >> 4, c4 = idx & 15;
                    int gq = 2 * (i0 + (row >> 2)) + q;
                    float4 v = make_float4(0.f, 0.f, 0.f, 0.f);
                    if (gq < nq) {
                        int sv = slt[4 * gq + (row & 3)];
                        if (!(sv & 0x8000))
                            v = __ldcg((const float4*)&childb[
                                s_tl[l * 128 + (sv & 127)] * PDEP + c4 * 4]);
                    }
                    *(float4*)&Cb[row * 68 + c4 * 4] = v;
                }
                __syncthreads();
                // compute
                int qd = tid >> 4, kg = tid & 15;
                int gq = 2 * (i0 + qd) + q;
                if (gq < nq) {
                    int sbase = 4 * gq;
                    int sv[4];
                    #pragma unroll
                    for (int ii = 0; ii < 4; ii++) sv[ii] = slt[sbase + ii];
                    int r = (sv[0] >> 7) & 63;
                    unsigned long long acc[4][2];
                    #pragma unroll
                    for (int ii = 0; ii < 4; ii++) { acc[ii][0] = 0ull; acc[ii][1] = 0ull; }
                    const float* wb = &g_W2T[(r * 1024 + kg) * 4];
                    const float* cb0 = &Cb[(4 * qd) * 68];
                    #pragma unroll 16
                    for (int d2 = 0; d2 < 32; d2++) {
                        ulonglong2 w0 = *(const ulonglong2*)&wb[d2 * 128];
                        ulonglong2 w1 = *(const ulonglong2*)&wb[d2 * 128 + 64];
                        #pragma unroll
                        for (int ii = 0; ii < 4; ii++) {
                            float2 cd = *(const float2*)&cb0[ii * 68 + 2 * d2];
                            unsigned long long cx = pack2(cd.x, cd.x);
                            unsigned long long cy = pack2(cd.y, cd.y);
                            fma2(acc[ii][0], w0.x, cx); fma2(acc[ii][0], w0.y, cy);
                            fma2(acc[ii][1], w1.x, cx); fma2(acc[ii][1], w1.y, cy);
                        }
                    }
                    #pragma unroll
                    for (int ii = 0; ii < 4; ii++) {
                        if (!(sv[ii] & 0x8000)) {
                            int e = sv[ii] & 127;
                            const float* pp = &g_pmsg[
                                ((int64_t)l * NEDGE + b * PE + e) * PDEP];
                            float2 pmL = __ldg((const float2*)&pp[2 * kg]);
                            float2 pmH = __ldg((const float2*)&pp[32 + 2 * kg]);
                            float a0, a1, a2, a3;
                            unpack2(acc[ii][0], a0, a1);
                            unpack2(acc[ii][1], a2, a3);
                            float2 lowv = make_float2(a0 + pmL.x, a1 + pmL.y);
                            float2 highv = make_float2(a2 + pmH.x, a3 + pmH.y);
                            float2 localv = (q == 0) ? lowv : highv;
                            float2 remotev = (q == 0) ? highv : lowv;
                            *(float2*)&Ms[e * 32 + 2 * kg] = localv;
                            st_dsmem64(peerMs + (e * 32 + 2 * kg) * 4,
                                       pack2(remotev.x, remotev.y));
                        }
                    }
                }
            }
            // sync A: all msgs (local + DSMEM-pushed) ready
            __syncthreads();
            if (tid == 0) {
                mbar_arrive_rel_cluster(peerBarA);
                mbar_wait_acq_cluster(barA, (unsigned int)((l - 1) & 1));
            }
            __syncthreads();
        }

        // ---- phase 2: segment average, own k-half ----
        {
            int wid = tid >> 5, lane = tid & 31;
            const int* hk = &s_hk[l * 128];
            const int* hx = &s_hx[l * 128];
            #pragma unroll
            for (int it = 0; it < 8; it++) {
                int p = wid * 8 + it;
                int h = hk[p];
                if (p > 0 && hk[p - 1] == h) continue;
                int len = 1;
                while (p + len < PE && hk[p + len] == h) len++;
                float s = 0.f;
                for (int j = 0; j < len; j++)
                    s += Ms[hx[p + j] * 32 + lane];
                __stcg(&childb[h * PDEP + q * 32 + lane], s * (1.f / (float)len));
            }
        }

        if (l + 1 < PL) {
            // sync B: child halves published (release covers stcg stores)
            __syncthreads();
            if (tid == 0) {
                mbar_arrive_rel_cluster(peerBarB);
                mbar_wait_acq_cluster(barB, (unsigned int)(l & 1));
            }
            __syncthreads();
        }
    }

    // ---- out write: own k-half for whole batch ----
    __syncthreads();
    #pragma unroll
    for (int t = 0; t < 16; t++) {
        int idx = tid + t * 512;             // 8192 float4
        int row = idx >> 3, c4 = idx & 7;
        const float* c = &childb[row * PDEP + q * 32 + c4 * 4];
        float4 v;
        v.x = __ldcg(&c[0]); v.y = __ldcg(&c[1]);
        v.z = __ldcg(&c[2]); v.w = __ldcg(&c[3]);
        *(float4*)&out[((int64_t)(b * PS + row)) * PF + PNODE + q * 32 + c4 * 4] = v;
    }
}

// ---------------------------------------------------------------------------
extern "C" void kernel_launch(void* const* d_in, const int* in_sizes, int n_in,
                              void* d_out, int out_size) {
    const float* ctx   = (const float*)d_in[0];
    const float* W     = (const float*)d_in[1];
    const int*   heads = (const int*)d_in[2];
    const int*   tails = (const int*)d_in[3];
    const int*   rels  = (const int*)d_in[4];
    float*       out   = (float*)d_out;

    cudaFuncSetAttribute(k_pmsg, cudaFuncAttributeMaxDynamicSharedMemorySize, PM_SMEM);
    cudaFuncSetAttribute(k_chain, cudaFuncAttributeMaxDynamicSharedMemorySize, CH_SMEM);

    k_flags<<<1, 64>>>();                             // launch 0 (tiny)
    k_prep<<<PREPB, 256>>>(rels, heads, W, ctx, out); // launch 1 (prep + init)
    k_pmsg<<<296, 512, PM_SMEM>>>(ctx, W, tails);     // launch 2 (occ 2/SM)
    k_chain<<<PB * 2, 512, CH_SMEM>>>(tails, out);    // launch 3
}

// round 17
// speedup vs baseline: 1.0603x; 1.0603x over previous
#include <cuda_runtime.h>
#include <cstdint>

#define PB 32
#define PS 1024
#define PNODE 256
#define PDEP 64
#define PR 50
#define PL 16
#define PE 128
#define PF 320
#define NEDGE (PB * PE)     // 4096
#define NTOT (PL * NEDGE)   // 65536
#define MAXCHUNK 640
#define PREPB 64
#define MAXSLOT 288

// ---------------- scratch --------------------------------------------------
__device__ float g_child[PB * PS * PDEP];
__device__ float g_pmsg[PL * NEDGE * PDEP];
__device__ float g_W2T[PR * 32 * 32 * 4];        // [r][d2][k2][4] quad layout
__device__ int   g_gsort[NTOT];
__device__ int   g_gcnt[PR];
__device__ int   g_gbase[PR + 1];
__device__ int   g_gcur[PR];
__device__ int   g_chunk_rel[MAXCHUNK];
__device__ int   g_chunk_start[MAXCHUNK];
__device__ int   g_chunk_ne[MAXCHUNK];
__device__ int   g_nchunks;
__device__ unsigned int g_ticket;
__device__ int   g_slots[PB * PL * MAXSLOT];     // (r<<7)|e, bit15 = pad
__device__ int   g_nslot[PB * PL];
__device__ int   g_hkey[NTOT];
__device__ int   g_hidx[NTOT];
__device__ unsigned int g_pbar;

// ---------------- helpers --------------------------------------------------
__device__ __forceinline__ void fma2(unsigned long long& acc,
                                     unsigned long long a, unsigned long long b) {
    asm("fma.rn.f32x2 %0, %1, %2, %0;" : "+l"(acc) : "l"(a), "l"(b));
}
__device__ __forceinline__ unsigned long long pack2(float x, float y) {
    unsigned long long v;
    asm("mov.b64 %0, {%1,%2};" : "=l"(v) : "r"(__float_as_uint(x)), "r"(__float_as_uint(y)));
    return v;
}
__device__ __forceinline__ void unpack2(unsigned long long v, float& x, float& y) {
    unsigned int lo, hi;
    asm("mov.b64 {%0,%1}, %2;" : "=r"(lo), "=r"(hi) : "l"(v));
    x = __uint_as_float(lo); y = __uint_as_float(hi);
}
__device__ __forceinline__ float hsum2(unsigned long long v) {
    float x, y; unpack2(v, x, y); return x + y;
}
__device__ __forceinline__ unsigned int smem_u32(const void* p) {
    return (unsigned int)__cvta_generic_to_shared(p);
}
__device__ __forceinline__ unsigned int mapa_sh(unsigned int addr, unsigned int rank) {
    unsigned int r;
    asm("mapa.shared::cluster.u32 %0, %1, %2;" : "=r"(r) : "r"(addr), "r"(rank));
    return r;
}
__device__ __forceinline__ void st_dsmem64(unsigned int addr, unsigned long long v) {
    asm volatile("st.shared::cluster.b64 [%0], %1;" :: "r"(addr), "l"(v) : "memory");
}
#define MBAR_INIT(addr, cnt) \
    asm volatile("mbarrier.init.shared.b64 [%0], %1;" :: "r"(addr), "r"(cnt) : "memory")
__device__ __forceinline__ void mbar_arrive_rel_cluster(unsigned int addr) {
    asm volatile("mbarrier.arrive.release.cluster.shared::cluster.b64 _, [%0];"
                 :: "r"(addr) : "memory");
}
__device__ __forceinline__ void mbar_wait_acq_cluster(unsigned int addr, unsigned int parity) {
    unsigned int done;
    do {
        asm volatile("{\n\t.reg .pred p;\n\t"
            "mbarrier.try_wait.parity.acquire.cluster.shared::cta.b64 p, [%1], %2, 0x989680;\n\t"
            "selp.b32 %0, 1, 0, p;\n\t}"
            : "=r"(done) : "r"(addr), "r"(parity) : "memory");
    } while (!done);
}
#define CLUSTER_ARRIVE() asm volatile("barrier.cluster.arrive.aligned;" ::: "memory")
#define CLUSTER_WAIT()   asm volatile("barrier.cluster.wait.aligned;" ::: "memory")

// ---------------- prep barrier ---------------------------------------------
__device__ __forceinline__ void psync(int* pc) {
    __syncthreads();
    (*pc)++;
    if (threadIdx.x == 0) {
        __threadfence();
        atomicAdd(&g_pbar, 1);
        unsigned int target = (unsigned int)(PREPB * (*pc));
        while (*(volatile unsigned int*)&g_pbar < target) { }
        __threadfence();
    }
    __syncthreads();
}

// ---------------- launch 0: preprocessing + init (merged) -------------------
// Flags (g_ticket/g_pbar/g_gcnt) are zero at module load and re-zeroed at the
// end of k_chain, so no flag-reset launch is needed.
__global__ void __launch_bounds__(256, 2)
k_prep(const int* __restrict__ rels, const int* __restrict__ heads,
       const float* __restrict__ W, const float* __restrict__ ctx,
       float* __restrict__ out) {
    int bid = blockIdx.x;
    int tid = threadIdx.x;
    int w = tid >> 5, lane = tid & 31;
    __shared__ int cnt[PR];
    __shared__ int hs2[2][128];
    __shared__ int srel[8][128];
    __shared__ int sb[PR], sch[PR];
    int pc = 0;

    // --- A-1: init work: out ctx-copy + child zero ---
    {
        const int64_t n_ctx = (int64_t)PB * PS * (PNODE / 4);
        const int64_t n_chd = (int64_t)PB * PS * (PDEP / 4);
        const int64_t total = n_ctx + n_chd;
        int64_t stride = (int64_t)PREPB * 256;
        for (int64_t i = (int64_t)bid * 256 + tid; i < total; i += stride) {
            if (i < n_ctx) {
                int64_t row = i >> 6, d4 = i & 63;
                float4 v = ((const float4*)ctx)[i];
                *(float4*)&out[row * PF + d4 * 4] = v;
            } else {
                ((float4*)g_child)[i - n_ctx] = make_float4(0.f, 0.f, 0.f, 0.f);
            }
        }
    }

    // --- A0: build W2T k-pair-quad layout: [r][d2][k2][4] ---
    for (int qi = bid * 256 + tid; qi < PR * 32 * 32; qi += PREPB * 256) {
        int r = qi >> 10, rem = qi & 1023;
        int d2 = rem >> 5, k2 = rem & 31;
        const float* Wb = W + ((int64_t)r * PDEP + 2 * k2) * PF + PNODE + 2 * d2;
        float4 v;
        v.x = __ldg(&Wb[0]);
        v.y = __ldg(&Wb[PF]);
        v.z = __ldg(&Wb[1]);
        v.w = __ldg(&Wb[PF + 1]);
        *(float4*)&g_W2T[qi * 4] = v;
    }

    // --- A1: global rel histogram ---
    if (tid < PR) cnt[tid] = 0;
    __syncthreads();
    int ebase = bid * 1024;
    #pragma unroll
    for (int t = 0; t < 4; t++)
        atomicAdd(&cnt[rels[ebase + tid + t * 256]], 1);
    __syncthreads();
    if (tid < PR && cnt[tid] > 0) atomicAdd(&g_gcnt[tid], cnt[tid]);

    // --- A2: per (b,l) padded rel-quad slot lists ---
    {
        int task = bid * 8 + w;           // 0..511 = b*PL + l
        int b = task >> 4, l = task & 15;
        #pragma unroll
        for (int t = 0; t < 4; t++)
            srel[w][lane + 32 * t] = rels[b * (PL * PE) + l * PE + lane + 32 * t];
        __syncwarp();
        int c0 = 0, c1 = 0;
        int r1 = lane + 32;
        for (int j = 0; j < PE; j++) {
            int rv = srel[w][j];
            c0 += (rv == lane);
            c1 += (rv == r1);
        }
        int p0 = (c0 + 3) & ~3;
        int p1 = (r1 < PR) ? ((c1 + 3) & ~3) : 0;
        int s0 = p0, s1 = p1;
        #pragma unroll
        for (int o = 1; o < 32; o <<= 1) {
            int x0 = __shfl_up_sync(0xffffffffu, s0, o);
            int x1 = __shfl_up_sync(0xffffffffu, s1, o);
            if (lane >= o) { s0 += x0; s1 += x1; }
        }
        int tot0 = __shfl_sync(0xffffffffu, s0, 31);
        int tot1 = __shfl_sync(0xffffffffu, s1, 31);
        int off0 = s0 - p0;
        int off1 = tot0 + s1 - p1;
        int* dst = &g_slots[task * MAXSLOT];
        int o0 = off0;
        for (int j = 0; j < PE; j++)
            if (srel[w][j] == lane) dst[o0++] = (lane << 7) | j;
        while (o0 < off0 + p0) dst[o0++] = (lane << 7) | 0x8000;
        if (p1 > 0) {
            int o1 = off1;
            for (int j = 0; j < PE; j++)
                if (srel[w][j] == r1) dst[o1++] = (r1 << 7) | j;
            while (o1 < off1 + p1) dst[o1++] = (r1 << 7) | 0x8000;
        }
        if (lane == 31) g_nslot[task] = tot0 + tot1;
    }

    // --- A3: head rank-sort ---
    #pragma unroll
    for (int t = 0; t < 4; t++) {
        int task = bid * 8 + t * 2 + (tid >> 7);
        int l = task >> 5, b = task & 31;
        int e = tid & 127;
        int h = heads[b * (PL * PE) + l * PE + e];
        hs2[tid >> 7][e] = h;
        __syncthreads();
        int rank = 0;
        #pragma unroll 8
        for (int o = 0; o < PE; o++) {
            int ho = hs2[tid >> 7][o];
            rank += (ho < h) || (ho == h && o < e);
        }
        int base = l * NEDGE + b * PE;
        g_hkey[base + rank] = h;
        g_hidx[base + rank] = e;
        __syncthreads();
    }

    psync(&pc);

    // --- B: prefix + chunk worklist (block 0) ---
    if (bid == 0) {
        if (tid == 0) {
            int s = 0, nc = 0;
            for (int r = 0; r < PR; r++) {
                sb[r] = s;
                sch[r] = nc;
                int c = g_gcnt[r];
                s += c;
                nc += (c + 127) >> 7;
            }
            g_gbase[PR] = s;
            g_nchunks = nc;
        }
        __syncthreads();
        if (tid < PR) {
            int b0 = sb[tid];
            g_gbase[tid] = b0;
            g_gcur[tid] = b0;
            int c = g_gcnt[tid];
            int nc0 = sch[tid];
            for (int o = 0, k = 0; o < c; o += 128, k++) {
                g_chunk_rel[nc0 + k] = tid;
                g_chunk_start[nc0 + k] = b0 + o;
                g_chunk_ne[nc0 + k] = min(128, c - o);
            }
        }
    }

    psync(&pc);

    // --- C: global scatter with range reservation ---
    __shared__ int rbase[PR], rcur[PR];
    if (tid < PR) rcur[tid] = 0;
    __syncthreads();
    if (tid < PR) rbase[tid] = (cnt[tid] > 0) ? atomicAdd(&g_gcur[tid], cnt[tid]) : 0;
    __syncthreads();
    #pragma unroll
    for (int t = 0; t < 4; t++) {
        int idx = ebase + tid + t * 256;
        int r = rels[idx];
        int pos = rbase[r] + atomicAdd(&rcur[r], 1);
        int b = idx >> 11, l = (idx >> 7) & 15, e = idx & 127;
        g_gsort[pos] = (l << 12) | (b << 7) | e;
    }
}

// ---------------- launch 1: pmsg (round-15 version: 512 thr, Ws staged) ----
#define PM_STRIDE 260
#define PM_SMEM ((64 * PM_STRIDE + 128 * PM_STRIDE) * (int)sizeof(float))

__global__ void __launch_bounds__(512, 1)
k_pmsg(const float* __restrict__ ctx, const float* __restrict__ W,
       const int* __restrict__ tails) {
    extern __shared__ float sm[];
    float* Ws = sm;
    float* Fs = sm + 64 * PM_STRIDE;
    __shared__ int seid[128];
    __shared__ int stail[128];
    __shared__ int s_chunk;
    int tid = threadIdx.x;

    while (true) {
        if (tid == 0) s_chunk = (int)atomicAdd(&g_ticket, 1u);
        __syncthreads();
        int c = s_chunk;
        if (c >= g_nchunks) break;
        int r = g_chunk_rel[c];
        int start = g_chunk_start[c];
        int ne = g_chunk_ne[c];

        if (tid < 128) {
            int v = (tid < ne) ? g_gsort[start + tid] : -1;
            seid[tid] = v;
            int tnode = 0;
            if (v >= 0) {
                int b = (v >> 7) & 31, l = v >> 12, e = v & 127;
                tnode = b * PS + tails[b * (PL * PE) + l * PE + e];
            }
            stail[tid] = tnode;
        }
        const float* Wg = W + (int64_t)r * PDEP * PF;
        #pragma unroll
        for (int t = 0; t < 8; t++) {
            int idx = tid + t * 512;              // 4096 float4
            int k = idx >> 6, cc = idx & 63;
            *(float4*)&Ws[k * PM_STRIDE + cc * 4] = *(const float4*)&Wg[k * PF + cc * 4];
        }
        __syncthreads();

        #pragma unroll
        for (int t = 0; t < 16; t++) {
            int idx = tid + t * 512;              // 8192 float4
            int row = idx >> 6, cc = idx & 63;
            float4 v = make_float4(0.f, 0.f, 0.f, 0.f);
            if (seid[row] >= 0)
                v = *(const float4*)&ctx[(int64_t)stail[row] * PNODE + cc * 4];
            *(float4*)&Fs[row * PM_STRIDE + cc * 4] = v;
        }
        __syncthreads();

        int eg = tid & 31;                        // e in {eg, +32, +64, +96}
        int kg = tid >> 5;                        // warp id = k-group: k 4kg..4kg+3
        unsigned long long acc[4][4];
        #pragma unroll
        for (int i = 0; i < 4; i++)
            #pragma unroll
            for (int j = 0; j < 4; j++) acc[i][j] = 0ull;

        #pragma unroll 4
        for (int d = 0; d < PNODE; d += 4) {
            ulonglong2 wv[4];
            #pragma unroll
            for (int j = 0; j < 4; j++)
                wv[j] = *(const ulonglong2*)&Ws[(4 * kg + j) * PM_STRIDE + d];
            #pragma unroll
            for (int i = 0; i < 4; i++) {
                ulonglong2 f = *(const ulonglong2*)&Fs[(eg + 32 * i) * PM_STRIDE + d];
                #pragma unroll
                for (int j = 0; j < 4; j++) {
                    fma2(acc[i][j], f.x, wv[j].x);
                    fma2(acc[i][j], f.y, wv[j].y);
                }
            }
        }

        #pragma unroll
        for (int i = 0; i < 4; i++) {
            int v = seid[eg + 32 * i];
            if (v >= 0) {
                int l = v >> 12, edge = v & 4095;
                float* dst = &g_pmsg[((int64_t)l * NEDGE + edge) * PDEP];
                #pragma unroll
                for (int j = 0; j < 4; j++)
                    dst[4 * kg + j] = hsum2(acc[i][j]);
            }
        }
        __syncthreads();
    }
}

// ---------------- launch 2: chain (round-12/15 exact) + flag reset ---------
#define CB_OFF 0
#define MS_OFF (128 * 68)
#define SLOT_OFF (MS_OFF + 128 * 32)
#define TL_OFF (SLOT_OFF + 16 * MAXSLOT)
#define HK_OFF (TL_OFF + 16 * 128)
#define HX_OFF (HK_OFF + 16 * 128)
#define NS_OFF (HX_OFF + 16 * 128)
#define CH_SMEM ((NS_OFF + 16) * (int)sizeof(float))

__global__ void __launch_bounds__(512, 1) __cluster_dims__(2, 1, 1)
k_chain(const int* __restrict__ tails, float* __restrict__ out) {
    extern __shared__ float sm[];
    float* Cb = sm + CB_OFF;                 // [128][68] gather tile
    float* Ms = sm + MS_OFF;                 // [128][32] own k-half msgs
    int* s_slot = (int*)(sm + SLOT_OFF);
    int* s_tl   = (int*)(sm + TL_OFF);
    int* s_hk   = (int*)(sm + HK_OFF);
    int* s_hx   = (int*)(sm + HX_OFF);
    int* s_ns   = (int*)(sm + NS_OFF);
    __shared__ unsigned long long s_mbar[2]; // [0]=A (msg), [1]=B (child)

    int b = blockIdx.x >> 1;
    unsigned int q = blockIdx.x & 1;
    int tid = threadIdx.x;

    unsigned int barA = smem_u32(&s_mbar[0]);
    unsigned int barB = smem_u32(&s_mbar[1]);
    if (tid == 0) { MBAR_INIT(barA, 1); MBAR_INIT(barB, 1); }

    // ---- prologue: stage all static per-layer data ----
    #pragma unroll
    for (int l2 = 0; l2 < PL; l2++)
        if (tid < MAXSLOT)
            s_slot[l2 * MAXSLOT + tid] = __ldg(&g_slots[(b * PL + l2) * MAXSLOT + tid]);
    #pragma unroll
    for (int t = 0; t < 4; t++) {
        int i = tid + t * 512;
        s_tl[i] = __ldg(&tails[b * (PL * PE) + i]);
    }
    #pragma unroll
    for (int l2 = 0; l2 < PL; l2++) {
        if (tid < 128) {
            s_hk[l2 * 128 + tid] = __ldg(&g_hkey[l2 * NEDGE + b * PE + tid]);
            s_hx[l2 * 128 + tid] = __ldg(&g_hidx[l2 * NEDGE + b * PE + tid]);
        }
    }
    if (tid < PL) s_ns[tid] = __ldg(&g_nslot[b * PL + tid]);
    __syncthreads();
    CLUSTER_ARRIVE(); CLUSTER_WAIT();       // peer mbarrier init visible

    unsigned int peerBarA = mapa_sh(barA, q ^ 1);
    unsigned int peerBarB = mapa_sh(barB, q ^ 1);
    unsigned int peerMs = mapa_sh(smem_u32(Ms), q ^ 1);

    float* childb = &g_child[b * PS * PDEP];

    for (int l = 0; l < PL; l++) {
        if (l == 0) {
            // Ms <- pmsg own k-half of all edges
            #pragma unroll
            for (int t = 0; t < 2; t++) {
                int idx = tid + t * 512;            // 1024 float4
                int e = idx >> 3, c4 = idx & 7;
                float4 v = __ldg((const float4*)&g_pmsg[
                    ((int64_t)(b * PE + e)) * PDEP + q * 32 + c4 * 4]);
                *(float4*)&Ms[e * 32 + c4 * 4] = v;
            }
            __syncthreads();
        } else {
            int nslot = s_ns[l];
            int nq = nslot >> 2;
            const int* slt = &s_slot[l * MAXSLOT];
            for (int i0 = 0; 2 * i0 + (int)q < nq; i0 += 32) {
                __syncthreads();
                // gather child rows for up to 32 own quads (128 rows)
                #pragma unroll
                for (int t = 0; t < 4; t++) {
                    int idx = tid + t * 512;
                    int row = idx >> 4, c4 = idx & 15;
                    int gq = 2 * (i0 + (row >> 2)) + q;
                    float4 v = make_float4(0.f, 0.f, 0.f, 0.f);
                    if (gq < nq) {
                        int sv = slt[4 * gq + (row & 3)];
                        if (!(sv & 0x8000))
                            v = __ldcg((const float4*)&childb[
                                s_tl[l * 128 + (sv & 127)] * PDEP + c4 * 4]);
                    }
                    *(float4*)&Cb[row * 68 + c4 * 4] = v;
                }
                __syncthreads();
                // compute
                int qd = tid >> 4, kg = tid & 15;
                int gq = 2 * (i0 + qd) + q;
                if (gq < nq) {
                    int sbase = 4 * gq;
                    int sv[4];
                    #pragma unroll
                    for (int ii = 0; ii < 4; ii++) sv[ii] = slt[sbase + ii];
                    int r = (sv[0] >> 7) & 63;
                    unsigned long long acc[4][2];
                    #pragma unroll
                    for (int ii = 0; ii < 4; ii++) { acc[ii][0] = 0ull; acc[ii][1] = 0ull; }
                    const float* wb = &g_W2T[(r * 1024 + kg) * 4];
                    const float* cb0 = &Cb[(4 * qd) * 68];
                    #pragma unroll 16
                    for (int d2 = 0; d2 < 32; d2++) {
                        ulonglong2 w0 = *(const ulonglong2*)&wb[d2 * 128];
                        ulonglong2 w1 = *(const ulonglong2*)&wb[d2 * 128 + 64];
                        #pragma unroll
                        for (int ii = 0; ii < 4; ii++) {
                            float2 cd = *(const float2*)&cb0[ii * 68 + 2 * d2];
                            unsigned long long cx = pack2(cd.x, cd.x);
                            unsigned long long cy = pack2(cd.y, cd.y);
                            fma2(acc[ii][0], w0.x, cx); fma2(acc[ii][0], w0.y, cy);
                            fma2(acc[ii][1], w1.x, cx); fma2(acc[ii][1], w1.y, cy);
                        }
                    }
                    #pragma unroll
                    for (int ii = 0; ii < 4; ii++) {
                        if (!(sv[ii] & 0x8000)) {
                            int e = sv[ii] & 127;
                            const float* pp = &g_pmsg[
                                ((int64_t)l * NEDGE + b * PE + e) * PDEP];
                            float2 pmL = __ldg((const float2*)&pp[2 * kg]);
                            float2 pmH = __ldg((const float2*)&pp[32 + 2 * kg]);
                            float a0, a1, a2, a3;
                            unpack2(acc[ii][0], a0, a1);
                            unpack2(acc[ii][1], a2, a3);
                            float2 lowv = make_float2(a0 + pmL.x, a1 + pmL.y);
                            float2 highv = make_float2(a2 + pmH.x, a3 + pmH.y);
                            float2 localv = (q == 0) ? lowv : highv;
                            float2 remotev = (q == 0) ? highv : lowv;
                            *(float2*)&Ms[e * 32 + 2 * kg] = localv;
                            st_dsmem64(peerMs + (e * 32 + 2 * kg) * 4,
                                       pack2(remotev.x, remotev.y));
                        }
                    }
                }
            }
            // sync A: all msgs (local + DSMEM-pushed) ready
            __syncthreads();
            if (tid == 0) {
                mbar_arrive_rel_cluster(peerBarA);
                mbar_wait_acq_cluster(barA, (unsigned int)((l - 1) & 1));
            }
            __syncthreads();
        }

        // ---- phase 2: segment average, own k-half ----
        {
            int wid = tid >> 5, lane = tid & 31;
            const int* hk = &s_hk[l * 128];
            const int* hx = &s_hx[l * 128];
            #pragma unroll
            for (int it = 0; it < 8; it++) {
                int p = wid * 8 + it;
                int h = hk[p];
                if (p > 0 && hk[p - 1] == h) continue;
                int len = 1;
                while (p + len < PE && hk[p + len] == h) len++;
                float s = 0.f;
                for (int j = 0; j < len; j++)
                    s += Ms[hx[p + j] * 32 + lane];
                __stcg(&childb[h * PDEP + q * 32 + lane], s * (1.f / (float)len));
            }
        }

        if (l + 1 < PL) {
            // sync B: child halves published (release covers stcg stores)
            __syncthreads();
            if (tid == 0) {
                mbar_arrive_rel_cluster(peerBarB);
                mbar_wait_acq_cluster(barB, (unsigned int)(l & 1));
            }
            __syncthreads();
        }
    }

    // ---- out write: own k-half for whole batch ----
    __syncthreads();
    #pragma unroll
    for (int t = 0; t < 16; t++) {
        int idx = tid + t * 512;             // 8192 float4
        int row = idx >> 3, c4 = idx & 7;
        const float* c = &childb[row * PDEP + q * 32 + c4 * 4];
        float4 v;
        v.x = __ldcg(&c[0]); v.y = __ldcg(&c[1]);
        v.z = __ldcg(&c[2]); v.w = __ldcg(&c[3]);
        *(float4*)&out[((int64_t)(b * PS + row)) * PF + PNODE + q * 32 + c4 * 4] = v;
    }

    // ---- epilogue: reset flags for the next graph replay (block 0) ----
    if (blockIdx.x == 0) {
        if (tid == 0) { g_ticket = 0; g_pbar = 0; }
        if (tid < PR) g_gcnt[tid] = 0;
    }
}

// ---------------------------------------------------------------------------
extern "C" void kernel_launch(void* const* d_in, const int* in_sizes, int n_in,
                              void* d_out, int out_size) {
    const float* ctx   = (const float*)d_in[0];
    const float* W     = (const float*)d_in[1];
    const int*   heads = (const int*)d_in[2];
    const int*   tails = (const int*)d_in[3];
    const int*   rels  = (const int*)d_in[4];
    float*       out   = (float*)d_out;

    cudaFuncSetAttribute(k_pmsg, cudaFuncAttributeMaxDynamicSharedMemorySize, PM_SMEM);
    cudaFuncSetAttribute(k_chain, cudaFuncAttributeMaxDynamicSharedMemorySize, CH_SMEM);

    k_prep<<<PREPB, 256>>>(rels, heads, W, ctx, out); // launch 0 (prep + init)
    k_pmsg<<<148, 512, PM_SMEM>>>(ctx, W, tails);     // launch 1
    k_chain<<<PB * 2, 512, CH_SMEM>>>(tails, out);    // launch 2
}